// round 14
// baseline (speedup 1.0000x reference)
#include <cuda_runtime.h>
#include <cuda_bf16.h>
#include <cstdint>
#include <cstddef>

#define TSTEPS 512
#define BATCH  64
#define NHID   1024
#define NCATS  1024
#define NCTA_SCAN 64
#define COLS   16      // h columns owned per scan CTA
#define KC     64      // K chunk for h streaming
#define NCHUNK 16      // NHID / KC
#define WPITCH 1028    // weight smem row pitch (conflict-free)
#define HPITCH 68      // h chunk smem row pitch (conflict-free)
// floats: 2*16*1028 + 2*64*68 + 64*16 + 2*64*17 + 16 = 44816 -> 179264 bytes
#define SCAN_SMEM_BYTES (44816 * 4)

// ---------------- device scratch (static allocation only) ----------------
__device__ float g_xz[TSTEPS * BATCH * NHID];   // [t][b][n]
__device__ float g_xh[TSTEPS * BATCH * NHID];   // [t][b][n]
__device__ float g_h [BATCH * NHID];            // hidden state [b][n]
__device__ unsigned g_cnt = 0;
__device__ volatile unsigned g_gen = 0;

// ---------------- helpers ----------------
__device__ __forceinline__ float tfbits(float x) {
    unsigned r; asm("cvt.rna.tf32.f32 %0, %1;" : "=r"(r) : "f"(x));
    return __uint_as_float(r);
}

__device__ __forceinline__ void mma_tf32(float* d,
                                         unsigned a0, unsigned a1, unsigned a2, unsigned a3,
                                         unsigned b0, unsigned b1) {
    asm volatile(
        "mma.sync.aligned.m16n8k8.row.col.f32.tf32.tf32.f32 "
        "{%0,%1,%2,%3}, {%4,%5,%6,%7}, {%8,%9}, {%0,%1,%2,%3};"
        : "+f"(d[0]), "+f"(d[1]), "+f"(d[2]), "+f"(d[3])
        : "r"(a0), "r"(a1), "r"(a2), "r"(a3), "r"(b0), "r"(b1));
}

// ======================================================================
// Kernel 1: xz/xh = x @ {Wz,Wh}^T.  M=32768 (b*512+t), K=1024, N=2*1024.
// grid = (16 n-blocks [8 Wz + 8 Wh], 256 m-blocks), 256 threads.
// Output layout [t][b][n].
// ======================================================================
__global__ __launch_bounds__(256) void pre_gemm(const float* __restrict__ x,
                                                const float* __restrict__ Wz,
                                                const float* __restrict__ Wh) {
    __shared__ float As[2][128][20];
    __shared__ float Bs[2][128][20];

    const int tid  = threadIdx.x;
    const int lane = tid & 31;
    const int warp = tid >> 5;
    const int wm   = warp >> 2;   // 0..1
    const int wn   = warp & 3;    // 0..3
    const int r4   = lane >> 2;   // 0..7
    const int c4   = lane & 3;    // 0..3

    const int nsel = blockIdx.x;  // <8 -> Wz slice, >=8 -> Wh slice
    const int m0   = blockIdx.y * 128;
    const float* W = (nsel < 8) ? (Wz + (size_t)nsel * 128 * NHID)
                                : (Wh + (size_t)(nsel - 8) * 128 * NHID);

    float acc[4][4][4];
#pragma unroll
    for (int i = 0; i < 4; ++i)
#pragma unroll
        for (int j = 0; j < 4; ++j)
#pragma unroll
            for (int e = 0; e < 4; ++e) acc[i][j][e] = 0.f;

    // first k-tile -> buffer 0
#pragma unroll
    for (int f = 0; f < 2; ++f) {
        int i = tid + 256 * f;
        int row = i >> 2;
        int cc  = (i & 3) * 4;
        float4 a = *(const float4*)(x + (size_t)(m0 + row) * NHID + cc);
        float4 b = *(const float4*)(W + (size_t)row * NHID + cc);
        float* da = &As[0][row][cc];
        float* db = &Bs[0][row][cc];
        da[0] = tfbits(a.x); da[1] = tfbits(a.y); da[2] = tfbits(a.z); da[3] = tfbits(a.w);
        db[0] = tfbits(b.x); db[1] = tfbits(b.y); db[2] = tfbits(b.z); db[3] = tfbits(b.w);
    }
    __syncthreads();

    for (int kb = 0; kb < 64; ++kb) {
        const int cur = kb & 1;
        float4 pa[2], pb[2];
        const bool pf = (kb < 63);
        if (pf) {
#pragma unroll
            for (int f = 0; f < 2; ++f) {
                int i = tid + 256 * f;
                int row = i >> 2;
                int cc  = (i & 3) * 4;
                pa[f] = *(const float4*)(x + (size_t)(m0 + row) * NHID + (kb + 1) * 16 + cc);
                pb[f] = *(const float4*)(W + (size_t)row * NHID + (kb + 1) * 16 + cc);
            }
        }
#pragma unroll
        for (int q = 0; q < 2; ++q) {
            const int kk = q * 8 + c4;
            unsigned af[4][4];
#pragma unroll
            for (int mt = 0; mt < 4; ++mt) {
                int r = wm * 64 + mt * 16 + r4;
                af[mt][0] = __float_as_uint(As[cur][r][kk]);
                af[mt][1] = __float_as_uint(As[cur][r + 8][kk]);
                af[mt][2] = __float_as_uint(As[cur][r][kk + 4]);
                af[mt][3] = __float_as_uint(As[cur][r + 8][kk + 4]);
            }
            unsigned bf[4][2];
#pragma unroll
            for (int nt = 0; nt < 4; ++nt) {
                int n = wn * 32 + nt * 8 + r4;
                bf[nt][0] = __float_as_uint(Bs[cur][n][kk]);
                bf[nt][1] = __float_as_uint(Bs[cur][n][kk + 4]);
            }
#pragma unroll
            for (int mt = 0; mt < 4; ++mt)
#pragma unroll
                for (int nt = 0; nt < 4; ++nt)
                    mma_tf32(acc[mt][nt], af[mt][0], af[mt][1], af[mt][2], af[mt][3],
                             bf[nt][0], bf[nt][1]);
        }
        if (pf) {
            const int nxt = (kb + 1) & 1;
#pragma unroll
            for (int f = 0; f < 2; ++f) {
                int i = tid + 256 * f;
                int row = i >> 2;
                int cc  = (i & 3) * 4;
                float* da = &As[nxt][row][cc];
                float* db = &Bs[nxt][row][cc];
                da[0] = tfbits(pa[f].x); da[1] = tfbits(pa[f].y);
                da[2] = tfbits(pa[f].z); da[3] = tfbits(pa[f].w);
                db[0] = tfbits(pb[f].x); db[1] = tfbits(pb[f].y);
                db[2] = tfbits(pb[f].z); db[3] = tfbits(pb[f].w);
            }
        }
        __syncthreads();
    }

    // epilogue: m = b*512 + t  ->  write [t][b][n]
    float* dstBase = (nsel < 8) ? g_xz : g_xh;
    const int ng0 = (nsel & 7) * 128 + wn * 32;
#pragma unroll
    for (int mt = 0; mt < 4; ++mt) {
        int m  = m0 + wm * 64 + mt * 16 + r4;
        int b1i = m >> 9, t1 = m & 511;
        size_t ro1 = ((size_t)t1 * BATCH + b1i) * NHID;
        int m2 = m + 8;
        int b2i = m2 >> 9, t2 = m2 & 511;
        size_t ro2 = ((size_t)t2 * BATCH + b2i) * NHID;
#pragma unroll
        for (int nt = 0; nt < 4; ++nt) {
            int n = ng0 + nt * 8 + 2 * c4;
            dstBase[ro1 + n]     = acc[mt][nt][0];
            dstBase[ro1 + n + 1] = acc[mt][nt][1];
            dstBase[ro2 + n]     = acc[mt][nt][2];
            dstBase[ro2 + n + 1] = acc[mt][nt][3];
        }
    }
}

// ---------------- software grid barrier (64 co-resident CTAs) ----------------
__device__ __forceinline__ void grid_barrier() {
    __syncthreads();
    if (threadIdx.x == 0) {
        unsigned my = g_gen;
        __threadfence();
        if (atomicAdd(&g_cnt, 1u) == NCTA_SCAN - 1) {
            g_cnt = 0;
            __threadfence();
            g_gen = my + 1;
        } else {
            while (g_gen == my) __nanosleep(64);
        }
    }
    __syncthreads();
}

// ======================================================================
// Kernel 2: persistent GRU scan. 64 CTAs x 256 threads, CTA owns 16 cols.
// Uz/Uh rows live in SMEM (tf32) for all 512 steps.
// ======================================================================
__global__ __launch_bounds__(256) void scan_kernel(const float* __restrict__ h0,
                                                   const float* __restrict__ Uz,
                                                   const float* __restrict__ Uh,
                                                   const float* __restrict__ bz) {
    extern __shared__ float sm[];
    float* Wz_s = sm;                            // 16 * 1028
    float* Wh_s = Wz_s + COLS * WPITCH;          // 16 * 1028
    float* hsb  = Wh_s + COLS * WPITCH;          // 2 * 64 * 68
    float* hown = hsb + 2 * BATCH * HPITCH;      // 64 * 16
    float* zs   = hown + BATCH * COLS;           // 64 * 17
    float* hts  = zs + BATCH * 17;               // 64 * 17
    float* bzs  = hts + BATCH * 17;              // 16

    const int tid  = threadIdx.x;
    const int lane = tid & 31;
    const int warp = tid >> 5;
    const int r4   = lane >> 2;
    const int c4   = lane & 3;
    const int n0   = blockIdx.x * COLS;

    // ---- prologue: load weights (tf32), bias, h0 slice ----
#pragma unroll 1
    for (int it = 0; it < 16; ++it) {
        int i   = tid + it * 256;     // over 16 rows * 256 float4
        int row = i >> 8;
        int cq  = (i & 255) * 4;
        float4 vz = *(const float4*)(Uz + (size_t)(n0 + row) * NHID + cq);
        float4 vh = *(const float4*)(Uh + (size_t)(n0 + row) * NHID + cq);
        float* dz = Wz_s + row * WPITCH + cq;
        float* dh = Wh_s + row * WPITCH + cq;
        dz[0] = tfbits(vz.x); dz[1] = tfbits(vz.y); dz[2] = tfbits(vz.z); dz[3] = tfbits(vz.w);
        dh[0] = tfbits(vh.x); dh[1] = tfbits(vh.y); dh[2] = tfbits(vh.z); dh[3] = tfbits(vh.w);
    }
    if (tid < COLS) bzs[tid] = bz[n0 + tid];
    for (int i = tid; i < BATCH * COLS; i += 256) {
        int b = i >> 4, j = i & 15;
        float v = h0[(size_t)b * NHID + n0 + j];
        hown[b * COLS + j] = v;
        g_h[b * NHID + n0 + j] = v;
    }
    __threadfence();
    grid_barrier();

    const float* Wsm = (warp < 4) ? Wz_s : Wh_s;
    float* Osm = (warp < 4) ? zs : hts;
    const int wrow = (warp & 3) * 16;

    for (int t = 0; t < TSTEPS; ++t) {
        float acc[2][4];
#pragma unroll
        for (int nt = 0; nt < 2; ++nt)
#pragma unroll
            for (int e = 0; e < 4; ++e) acc[nt][e] = 0.f;

        // stage chunk 0 into buffer 0 (ldcg: L2 is the coherence point)
#pragma unroll
        for (int f = 0; f < 4; ++f) {
            int i   = tid + 256 * f;
            int row = i >> 4;
            int cc  = (i & 15) * 4;
            float4 v = __ldcg((const float4*)(g_h + row * NHID + cc));
            float* d = hsb + row * HPITCH + cc;
            d[0] = tfbits(v.x); d[1] = tfbits(v.y); d[2] = tfbits(v.z); d[3] = tfbits(v.w);
        }
        __syncthreads();

        for (int kc = 0; kc < NCHUNK; ++kc) {
            float4 pre[4];
            const bool pf = (kc + 1 < NCHUNK);
            if (pf) {
#pragma unroll
                for (int f = 0; f < 4; ++f) {
                    int i   = tid + 256 * f;
                    int row = i >> 4;
                    int cc  = (i & 15) * 4;
                    pre[f] = __ldcg((const float4*)(g_h + row * NHID + (kc + 1) * KC + cc));
                }
            }
            const float* hb = hsb + (kc & 1) * BATCH * HPITCH;
#pragma unroll
            for (int q = 0; q < 8; ++q) {
                const int kk = q * 8 + c4;
                unsigned a0 = __float_as_uint(hb[(wrow + r4) * HPITCH + kk]);
                unsigned a1 = __float_as_uint(hb[(wrow + r4 + 8) * HPITCH + kk]);
                unsigned a2 = __float_as_uint(hb[(wrow + r4) * HPITCH + kk + 4]);
                unsigned a3 = __float_as_uint(hb[(wrow + r4 + 8) * HPITCH + kk + 4]);
                const int kg = kc * KC + kk;
#pragma unroll
                for (int nt = 0; nt < 2; ++nt) {
                    unsigned b0 = __float_as_uint(Wsm[(nt * 8 + r4) * WPITCH + kg]);
                    unsigned b1 = __float_as_uint(Wsm[(nt * 8 + r4) * WPITCH + kg + 4]);
                    mma_tf32(acc[nt], a0, a1, a2, a3, b0, b1);
                }
            }
            if (pf) {
                float* d0 = hsb + ((kc + 1) & 1) * BATCH * HPITCH;
#pragma unroll
                for (int f = 0; f < 4; ++f) {
                    int i   = tid + 256 * f;
                    int row = i >> 4;
                    int cc  = (i & 15) * 4;
                    float* d = d0 + row * HPITCH + cc;
                    d[0] = tfbits(pre[f].x); d[1] = tfbits(pre[f].y);
                    d[2] = tfbits(pre[f].z); d[3] = tfbits(pre[f].w);
                }
            }
            __syncthreads();
        }

        // accumulators -> smem (z warps -> zs, htilde warps -> hts)
        {
            int r  = wrow + r4;
            int cb = 2 * c4;
#pragma unroll
            for (int nt = 0; nt < 2; ++nt) {
                Osm[r * 17 + nt * 8 + cb]           = acc[nt][0];
                Osm[r * 17 + nt * 8 + cb + 1]       = acc[nt][1];
                Osm[(r + 8) * 17 + nt * 8 + cb]     = acc[nt][2];
                Osm[(r + 8) * 17 + nt * 8 + cb + 1] = acc[nt][3];
            }
        }
        __syncthreads();

        // pointwise GRU update on owned slice
        {
            const int j   = tid & 15;
            const int b0i = tid >> 4;
            const size_t xbase = (size_t)t * (BATCH * NHID);
#pragma unroll
            for (int s = 0; s < 4; ++s) {
                int b = b0i + s * 16;
                float zin = zs[b * 17 + j] + g_xz[xbase + (size_t)b * NHID + n0 + j] + bzs[j];
                float z   = 1.f / (1.f + __expf(-zin));
                float htv = tanhf(hts[b * 17 + j] + g_xh[xbase + (size_t)b * NHID + n0 + j]);
                float hv  = hown[b * COLS + j];
                float hn  = hv + z * (htv - hv);
                hown[b * COLS + j] = hn;
                g_h[b * NHID + n0 + j] = hn;
            }
        }
        __threadfence();
        grid_barrier();
    }
}

// ======================================================================
// Kernel 3: out = hT @ Wout^T  (64 x 1024 x 1024), fp32 smem-tiled.
// grid = 16 (64-col tiles), 256 threads.
// ======================================================================
__global__ __launch_bounds__(256) void out_gemm(const float* __restrict__ Wout,
                                                float* __restrict__ out) {
    __shared__ float Hs[64][65];
    __shared__ float Ws[64][65];
    const int tid = threadIdx.x;
    const int n0  = blockIdx.x * 64;
    const int nl  = tid & 63;
    const int bb  = (tid >> 6) * 16;

    float acc[16];
#pragma unroll
    for (int i = 0; i < 16; ++i) acc[i] = 0.f;

    for (int kb = 0; kb < 16; ++kb) {
        __syncthreads();
        for (int i = tid; i < 4096; i += 256) {
            int r = i >> 6, c = i & 63;
            Hs[r][c] = g_h[(size_t)r * NHID + kb * 64 + c];
            Ws[r][c] = Wout[(size_t)(n0 + r) * NHID + kb * 64 + c];
        }
        __syncthreads();
#pragma unroll 8
        for (int kk = 0; kk < 64; ++kk) {
            float wv = Ws[nl][kk];
#pragma unroll
            for (int i = 0; i < 16; ++i) acc[i] += Hs[bb + i][kk] * wv;
        }
    }
#pragma unroll
    for (int i = 0; i < 16; ++i)
        out[(size_t)(bb + i) * NCATS + n0 + nl] = acc[i];
}

// ======================================================================
extern "C" void kernel_launch(void* const* d_in, const int* in_sizes, int n_in,
                              void* d_out, int out_size) {
    (void)in_sizes; (void)n_in; (void)out_size;
    const float* x    = (const float*)d_in[0];
    const float* h0   = (const float*)d_in[1];
    const float* Wh   = (const float*)d_in[2];
    const float* Wz   = (const float*)d_in[3];
    // d_in[4] = Wr (unused: r gate is dead code in the reference)
    const float* Uh   = (const float*)d_in[5];
    const float* Uz   = (const float*)d_in[6];
    // d_in[7] = Ur (unused)
    const float* bz   = (const float*)d_in[8];
    // d_in[9] = br (unused)
    const float* Wout = (const float*)d_in[10];

    cudaFuncSetAttribute(scan_kernel, cudaFuncAttributeMaxDynamicSharedMemorySize,
                         SCAN_SMEM_BYTES);

    pre_gemm<<<dim3(16, 256), 256>>>(x, Wz, Wh);
    scan_kernel<<<NCTA_SCAN, 256, SCAN_SMEM_BYTES>>>(h0, Uz, Uh, bz);
    out_gemm<<<16, 256>>>(Wout, (float*)d_out);
}